// round 5
// baseline (speedup 1.0000x reference)
#include <cuda_runtime.h>
#include <cuda_bf16.h>

#define N_NODES   100000
#define N_EDGES   1600000
#define NUM_RELS  200
#define IN_FEAT   20
#define OUT_FEAT  20

// Fixed-capacity relation bins: mean 8000 edges/rel, sd ~89. CAP = +7.9 sigma.
#define CAP        8704
#define TOTAL_SLOTS (NUM_RELS * CAP)

// SMEM layout for edge kernel (floats): W stride 25 (unpadded), gw, bias.
#define SM_W_OFF   0
#define SM_GW_OFF  (NUM_RELS * 100)              // 20000
#define SM_B_OFF   (SM_GW_OFF + NUM_RELS * 20)   // 24000
#define SM_FLOATS  (SM_B_OFF + NUM_RELS * 20)    // 28000
#define SM_BYTES   (SM_FLOATS * 4)               // 112000 -> 2 CTAs/SM

// ---------------------------------------------------------------------------
// Static scratch (no cudaMalloc allowed)
// ---------------------------------------------------------------------------
__device__ int  g_cursor[NUM_RELS];
__device__ int2 g_edges_s[TOTAL_SLOTS];   // (src, dst) in rel-strided bins

__device__ __forceinline__ void red_add_v4(float* addr, float a, float b, float c, float d) {
    asm volatile("red.global.add.v4.f32 [%0], {%1, %2, %3, %4};"
                 :: "l"(addr), "f"(a), "f"(b), "f"(c), "f"(d)
                 : "memory");
}

// ---------------------------------------------------------------------------
// Kernel A: out[n,:] = h[n,:] @ loop_weight   (also zeroes bin cursors)
// ---------------------------------------------------------------------------
__global__ void loop_msg_kernel(const float* __restrict__ h,
                                const float* __restrict__ loop_w,
                                float* __restrict__ out) {
    __shared__ float w[IN_FEAT * OUT_FEAT];
    for (int i = threadIdx.x; i < IN_FEAT * OUT_FEAT; i += blockDim.x)
        w[i] = loop_w[i];
    if (blockIdx.x == 0 && threadIdx.x < NUM_RELS)
        g_cursor[threadIdx.x] = 0;
    __syncthreads();

    int n = blockIdx.x * blockDim.x + threadIdx.x;
    if (n >= N_NODES) return;

    const float4* h4 = reinterpret_cast<const float4*>(h + (size_t)n * IN_FEAT);
    float x[IN_FEAT];
#pragma unroll
    for (int i = 0; i < 5; i++) {
        float4 t = h4[i];
        x[4*i+0] = t.x; x[4*i+1] = t.y; x[4*i+2] = t.z; x[4*i+3] = t.w;
    }

    float4 acc[5];
#pragma unroll
    for (int k = 0; k < 5; k++) acc[k] = make_float4(0.f, 0.f, 0.f, 0.f);

#pragma unroll
    for (int i = 0; i < IN_FEAT; i++) {
        float xi = x[i];
        const float4* wr = reinterpret_cast<const float4*>(w + i * OUT_FEAT);
#pragma unroll
        for (int k = 0; k < 5; k++) {
            float4 wv = wr[k];
            acc[k].x = fmaf(xi, wv.x, acc[k].x);
            acc[k].y = fmaf(xi, wv.y, acc[k].y);
            acc[k].z = fmaf(xi, wv.z, acc[k].z);
            acc[k].w = fmaf(xi, wv.w, acc[k].w);
        }
    }

    float4* o4 = reinterpret_cast<float4*>(out + (size_t)n * OUT_FEAT);
#pragma unroll
    for (int k = 0; k < 5; k++) o4[k] = acc[k];
}

// ---------------------------------------------------------------------------
// Single-pass binning: direct global-atomic slot reservation.
// 1.6M atomics spread over 200 L2 counters (~0.85cyc/op per address chain).
// ---------------------------------------------------------------------------
__global__ void scatter_kernel(const int* __restrict__ src,
                               const int* __restrict__ dst,
                               const int* __restrict__ et) {
    const int n4 = N_EDGES / 4;
    const int stride = gridDim.x * blockDim.x;
    const int4* et4  = reinterpret_cast<const int4*>(et);
    const int4* src4 = reinterpret_cast<const int4*>(src);
    const int4* dst4 = reinterpret_cast<const int4*>(dst);

    for (int b = blockIdx.x * blockDim.x + threadIdx.x; b < n4; b += stride) {
        int4 r = et4[b];
        int4 s = src4[b];
        int4 d = dst4[b];
        int p0 = atomicAdd(&g_cursor[r.x], 1);
        int p1 = atomicAdd(&g_cursor[r.y], 1);
        int p2 = atomicAdd(&g_cursor[r.z], 1);
        int p3 = atomicAdd(&g_cursor[r.w], 1);
        g_edges_s[r.x * CAP + p0] = make_int2(s.x, d.x);
        g_edges_s[r.y * CAP + p1] = make_int2(s.y, d.y);
        g_edges_s[r.z * CAP + p2] = make_int2(s.z, d.z);
        g_edges_s[r.w * CAP + p3] = make_int2(s.w, d.w);
    }
}

// ---------------------------------------------------------------------------
// Edge kernel over bin slot-space. 2 CTAs/SM (112KB SMEM each), rel is
// warp-uniform within a bin so all table reads are conflict-free broadcasts.
// Edge record + cursor loads issued in parallel (no serial dependency).
// ---------------------------------------------------------------------------
__global__ __launch_bounds__(512, 2)
void edge_kernel(const float* __restrict__ h,
                 const float* __restrict__ weight,      // [200, 100]
                 const float* __restrict__ bias_term,   // [200, 20]
                 const float* __restrict__ gate_weight, // [200, 20]
                 const float* __restrict__ gate_bias,   // [200]
                 float* __restrict__ out) {
    extern __shared__ float sm[];
    float* Wsh  = sm + SM_W_OFF;
    float* gwsh = sm + SM_GW_OFF;
    float* bsh  = sm + SM_B_OFF;

    for (int i = threadIdx.x; i < NUM_RELS * 100; i += blockDim.x) Wsh[i]  = weight[i];
    for (int i = threadIdx.x; i < NUM_RELS * 20;  i += blockDim.x) gwsh[i] = gate_weight[i];
    for (int i = threadIdx.x; i < NUM_RELS * 20;  i += blockDim.x) bsh[i]  = bias_term[i];
    __syncthreads();

    const int stride = gridDim.x * blockDim.x;
    for (int slot = blockIdx.x * blockDim.x + threadIdx.x; slot < TOTAL_SLOTS; slot += stride) {
        int r   = slot / CAP;
        int idx = slot - r * CAP;

        // Issue all three loads concurrently; record read is always safe
        // (static array), validity decided afterwards.
        int2 ed  = __ldg(&g_edges_s[slot]);
        int cnt  = __ldg(&g_cursor[r]);
        float gb = __ldg(&gate_bias[r]);
        if (idx >= cnt) continue;

        int s = ed.x, d = ed.y;

        // gather source features (5 outstanding LDG.128)
        const float4* h4 = reinterpret_cast<const float4*>(h + (size_t)s * IN_FEAT);
        float4 t[5];
#pragma unroll
        for (int i = 0; i < 5; i++) t[i] = __ldg(&h4[i]);
        float x[IN_FEAT];
#pragma unroll
        for (int i = 0; i < 5; i++) {
            x[4*i+0] = t[i].x; x[4*i+1] = t[i].y; x[4*i+2] = t[i].z; x[4*i+3] = t[i].w;
        }

        // gate = sigmoid(dot(x, gw[r]) + gb[r])
        const float4* gw4 = reinterpret_cast<const float4*>(gwsh + r * 20);
        float g = gb;
#pragma unroll
        for (int k = 0; k < 5; k++) {
            float4 wv = gw4[k];
            g = fmaf(x[4*k+0], wv.x, g);
            g = fmaf(x[4*k+1], wv.y, g);
            g = fmaf(x[4*k+2], wv.z, g);
            g = fmaf(x[4*k+3], wv.w, g);
        }
        float gate = 1.0f / (1.0f + __expf(-g));

        // block-diagonal matmul: scalar broadcast LDS of W rows
        float m[OUT_FEAT];
        const float* Wr = Wsh + r * 100;
#pragma unroll
        for (int b = 0; b < 4; b++) {
            const float* wb = Wr + b * 25;
            float x0 = x[b*5+0], x1 = x[b*5+1], x2 = x[b*5+2], x3 = x[b*5+3], x4 = x[b*5+4];
#pragma unroll
            for (int o = 0; o < 5; o++) {
                float acc =        x0 * wb[o];
                acc = fmaf(x1, wb[5  + o], acc);
                acc = fmaf(x2, wb[10 + o], acc);
                acc = fmaf(x3, wb[15 + o], acc);
                acc = fmaf(x4, wb[20 + o], acc);
                m[b*5 + o] = acc;
            }
        }

        // gated + biased vector scatter-add
        const float4* br4 = reinterpret_cast<const float4*>(bsh + r * 20);
        float* op = out + (size_t)d * OUT_FEAT;
#pragma unroll
        for (int k = 0; k < 5; k++) {
            float4 bv = br4[k];
            red_add_v4(op + 4*k,
                       gate * (m[4*k+0] + bv.x),
                       gate * (m[4*k+1] + bv.y),
                       gate * (m[4*k+2] + bv.z),
                       gate * (m[4*k+3] + bv.w));
        }
    }
}

// ---------------------------------------------------------------------------
// Kernel C: in-place ReLU, 4 independent float4s per thread for MLP
// ---------------------------------------------------------------------------
__global__ void relu_kernel(float* __restrict__ out, int n4) {
    float4* p = reinterpret_cast<float4*>(out);
    int base = blockIdx.x * blockDim.x * 4 + threadIdx.x;
    int bs = blockDim.x;
    float4 v[4];
    int   ok[4];
#pragma unroll
    for (int k = 0; k < 4; k++) {
        int i = base + k * bs;
        ok[k] = (i < n4);
        if (ok[k]) v[k] = p[i];
    }
#pragma unroll
    for (int k = 0; k < 4; k++) {
        if (ok[k]) {
            int i = base + k * bs;
            float4 w = v[k];
            w.x = fmaxf(w.x, 0.0f);
            w.y = fmaxf(w.y, 0.0f);
            w.z = fmaxf(w.z, 0.0f);
            w.w = fmaxf(w.w, 0.0f);
            p[i] = w;
        }
    }
}

// ---------------------------------------------------------------------------
// Launch
// ---------------------------------------------------------------------------
extern "C" void kernel_launch(void* const* d_in, const int* in_sizes, int n_in,
                              void* d_out, int out_size) {
    const float* h           = (const float*)d_in[0];
    const float* weight      = (const float*)d_in[1];
    const float* bias_term   = (const float*)d_in[2];
    const float* gate_weight = (const float*)d_in[3];
    const float* gate_bias   = (const float*)d_in[4];
    const float* loop_weight = (const float*)d_in[5];
    const int*   edge_src    = (const int*)d_in[6];
    const int*   edge_dst    = (const int*)d_in[7];
    const int*   etype       = (const int*)d_in[8];
    float* out = (float*)d_out;

    // A: self-loop message into out (+ zero bin cursors)
    loop_msg_kernel<<<(N_NODES + 255) / 256, 256>>>(h, loop_weight, out);

    // Single-pass binning by relation into fixed-capacity bins
    scatter_kernel<<<592, 256>>>(edge_src, edge_dst, etype);

    // Edge kernel, 2 CTAs/SM
    cudaFuncSetAttribute(edge_kernel, cudaFuncAttributeMaxDynamicSharedMemorySize, SM_BYTES);
    edge_kernel<<<296, 512, SM_BYTES>>>(h, weight, bias_term, gate_weight, gate_bias, out);

    // ReLU in place (4 float4 per thread)
    int n4 = (N_NODES * OUT_FEAT) / 4;
    relu_kernel<<<(n4 + 1023) / 1024, 256>>>(out, n4);
}

// round 6
// speedup vs baseline: 4.9369x; 4.9369x over previous
#include <cuda_runtime.h>
#include <cuda_bf16.h>

#define N_NODES   100000
#define N_EDGES   1600000
#define NUM_RELS  200
#define IN_FEAT   20
#define OUT_FEAT  20

// Fixed-capacity relation bins: mean 8000 edges/rel, sd ~89. CAP = +7.9 sigma.
#define CAP        8704
#define TOTAL_SLOTS (NUM_RELS * CAP)

// SMEM layout for edge kernel (floats): W stride 25 (unpadded), gw, bias.
#define SM_W_OFF   0
#define SM_GW_OFF  (NUM_RELS * 100)              // 20000
#define SM_B_OFF   (SM_GW_OFF + NUM_RELS * 20)   // 24000
#define SM_FLOATS  (SM_B_OFF + NUM_RELS * 20)    // 28000
#define SM_BYTES   (SM_FLOATS * 4)               // 112000 -> 2 CTAs/SM

// ---------------------------------------------------------------------------
// Static scratch (no cudaMalloc allowed)
// ---------------------------------------------------------------------------
__device__ int  g_cursor[NUM_RELS];
__device__ int2 g_edges_s[TOTAL_SLOTS];   // (src, dst) in rel-strided bins

__device__ __forceinline__ void red_add_v4(float* addr, float a, float b, float c, float d) {
    asm volatile("red.global.add.v4.f32 [%0], {%1, %2, %3, %4};"
                 :: "l"(addr), "f"(a), "f"(b), "f"(c), "f"(d)
                 : "memory");
}

// ---------------------------------------------------------------------------
// Kernel A: out[n,:] = h[n,:] @ loop_weight   (also zeroes bin cursors)
// ---------------------------------------------------------------------------
__global__ void loop_msg_kernel(const float* __restrict__ h,
                                const float* __restrict__ loop_w,
                                float* __restrict__ out) {
    __shared__ float w[IN_FEAT * OUT_FEAT];
    for (int i = threadIdx.x; i < IN_FEAT * OUT_FEAT; i += blockDim.x)
        w[i] = loop_w[i];
    if (blockIdx.x == 0 && threadIdx.x < NUM_RELS)
        g_cursor[threadIdx.x] = 0;
    __syncthreads();

    int n = blockIdx.x * blockDim.x + threadIdx.x;
    if (n >= N_NODES) return;

    const float4* h4 = reinterpret_cast<const float4*>(h + (size_t)n * IN_FEAT);
    float x[IN_FEAT];
#pragma unroll
    for (int i = 0; i < 5; i++) {
        float4 t = h4[i];
        x[4*i+0] = t.x; x[4*i+1] = t.y; x[4*i+2] = t.z; x[4*i+3] = t.w;
    }

    float4 acc[5];
#pragma unroll
    for (int k = 0; k < 5; k++) acc[k] = make_float4(0.f, 0.f, 0.f, 0.f);

#pragma unroll
    for (int i = 0; i < IN_FEAT; i++) {
        float xi = x[i];
        const float4* wr = reinterpret_cast<const float4*>(w + i * OUT_FEAT);
#pragma unroll
        for (int k = 0; k < 5; k++) {
            float4 wv = wr[k];
            acc[k].x = fmaf(xi, wv.x, acc[k].x);
            acc[k].y = fmaf(xi, wv.y, acc[k].y);
            acc[k].z = fmaf(xi, wv.z, acc[k].z);
            acc[k].w = fmaf(xi, wv.w, acc[k].w);
        }
    }

    float4* o4 = reinterpret_cast<float4*>(out + (size_t)n * OUT_FEAT);
#pragma unroll
    for (int k = 0; k < 5; k++) o4[k] = acc[k];
}

// ---------------------------------------------------------------------------
// Block-aggregated binning: SMEM histogram per block, ONE returned global
// atomic per (block, rel) to reserve bin space, then SMEM-offset scatter.
// (Per-edge returned global atomics to 200 hot addresses serialize at full
//  ATOMG latency — measured 4x whole-run regression. Never do that.)
// ---------------------------------------------------------------------------
__global__ void scatter_kernel(const int* __restrict__ src,
                               const int* __restrict__ dst,
                               const int* __restrict__ et) {
    __shared__ int cnt[NUM_RELS];
    __shared__ int base[NUM_RELS];
    const int per_block = 3128;  // multiple of 4; 512 blocks cover 1.6M
    int lo = blockIdx.x * per_block;
    int hi = lo + per_block; if (hi > N_EDGES) hi = N_EDGES;
    if (lo >= N_EDGES) return;

    for (int i = threadIdx.x; i < NUM_RELS; i += blockDim.x) cnt[i] = 0;
    __syncthreads();

    for (int b = lo + threadIdx.x * 4; b < hi; b += blockDim.x * 4) {
        if (b + 3 < hi) {
            int4 v = *reinterpret_cast<const int4*>(et + b);
            atomicAdd(&cnt[v.x], 1); atomicAdd(&cnt[v.y], 1);
            atomicAdd(&cnt[v.z], 1); atomicAdd(&cnt[v.w], 1);
        } else {
            for (int e = b; e < hi; e++) atomicAdd(&cnt[et[e]], 1);
        }
    }
    __syncthreads();
    for (int i = threadIdx.x; i < NUM_RELS; i += blockDim.x) {
        int c = cnt[i];
        base[i] = c ? atomicAdd(&g_cursor[i], c) : 0;
        cnt[i] = 0;
    }
    __syncthreads();

    for (int b = lo + threadIdx.x * 4; b < hi; b += blockDim.x * 4) {
        if (b + 3 < hi) {
            int4 r = *reinterpret_cast<const int4*>(et + b);
            int4 s = *reinterpret_cast<const int4*>(src + b);
            int4 d = *reinterpret_cast<const int4*>(dst + b);
            int p0 = base[r.x] + atomicAdd(&cnt[r.x], 1);
            g_edges_s[r.x * CAP + p0] = make_int2(s.x, d.x);
            int p1 = base[r.y] + atomicAdd(&cnt[r.y], 1);
            g_edges_s[r.y * CAP + p1] = make_int2(s.y, d.y);
            int p2 = base[r.z] + atomicAdd(&cnt[r.z], 1);
            g_edges_s[r.z * CAP + p2] = make_int2(s.z, d.z);
            int p3 = base[r.w] + atomicAdd(&cnt[r.w], 1);
            g_edges_s[r.w * CAP + p3] = make_int2(s.w, d.w);
        } else {
            for (int e = b; e < hi; e++) {
                int r = et[e];
                int p = base[r] + atomicAdd(&cnt[r], 1);
                g_edges_s[r * CAP + p] = make_int2(src[e], dst[e]);
            }
        }
    }
}

// ---------------------------------------------------------------------------
// Edge kernel over bin slot-space. 2 CTAs/SM (112KB SMEM each), rel is
// warp-uniform within a bin so all table reads are conflict-free broadcasts.
// Edge record + cursor + gate_bias loads issued in parallel.
// ---------------------------------------------------------------------------
__global__ __launch_bounds__(512, 2)
void edge_kernel(const float* __restrict__ h,
                 const float* __restrict__ weight,      // [200, 100]
                 const float* __restrict__ bias_term,   // [200, 20]
                 const float* __restrict__ gate_weight, // [200, 20]
                 const float* __restrict__ gate_bias,   // [200]
                 float* __restrict__ out) {
    extern __shared__ float sm[];
    float* Wsh  = sm + SM_W_OFF;
    float* gwsh = sm + SM_GW_OFF;
    float* bsh  = sm + SM_B_OFF;

    for (int i = threadIdx.x; i < NUM_RELS * 100; i += blockDim.x) Wsh[i]  = weight[i];
    for (int i = threadIdx.x; i < NUM_RELS * 20;  i += blockDim.x) gwsh[i] = gate_weight[i];
    for (int i = threadIdx.x; i < NUM_RELS * 20;  i += blockDim.x) bsh[i]  = bias_term[i];
    __syncthreads();

    const int stride = gridDim.x * blockDim.x;
    for (int slot = blockIdx.x * blockDim.x + threadIdx.x; slot < TOTAL_SLOTS; slot += stride) {
        int r   = slot / CAP;
        int idx = slot - r * CAP;

        // Issue all three loads concurrently; record read is always safe
        // (static array), validity decided afterwards.
        int2 ed  = __ldg(&g_edges_s[slot]);
        int cnt  = __ldg(&g_cursor[r]);
        float gb = __ldg(&gate_bias[r]);
        if (idx >= cnt) continue;

        int s = ed.x, d = ed.y;

        // gather source features (5 outstanding LDG.128)
        const float4* h4 = reinterpret_cast<const float4*>(h + (size_t)s * IN_FEAT);
        float4 t[5];
#pragma unroll
        for (int i = 0; i < 5; i++) t[i] = __ldg(&h4[i]);
        float x[IN_FEAT];
#pragma unroll
        for (int i = 0; i < 5; i++) {
            x[4*i+0] = t[i].x; x[4*i+1] = t[i].y; x[4*i+2] = t[i].z; x[4*i+3] = t[i].w;
        }

        // gate = sigmoid(dot(x, gw[r]) + gb[r])
        const float4* gw4 = reinterpret_cast<const float4*>(gwsh + r * 20);
        float g = gb;
#pragma unroll
        for (int k = 0; k < 5; k++) {
            float4 wv = gw4[k];
            g = fmaf(x[4*k+0], wv.x, g);
            g = fmaf(x[4*k+1], wv.y, g);
            g = fmaf(x[4*k+2], wv.z, g);
            g = fmaf(x[4*k+3], wv.w, g);
        }
        float gate = 1.0f / (1.0f + __expf(-g));

        // block-diagonal matmul: scalar broadcast LDS of W rows
        float m[OUT_FEAT];
        const float* Wr = Wsh + r * 100;
#pragma unroll
        for (int b = 0; b < 4; b++) {
            const float* wb = Wr + b * 25;
            float x0 = x[b*5+0], x1 = x[b*5+1], x2 = x[b*5+2], x3 = x[b*5+3], x4 = x[b*5+4];
#pragma unroll
            for (int o = 0; o < 5; o++) {
                float acc =        x0 * wb[o];
                acc = fmaf(x1, wb[5  + o], acc);
                acc = fmaf(x2, wb[10 + o], acc);
                acc = fmaf(x3, wb[15 + o], acc);
                acc = fmaf(x4, wb[20 + o], acc);
                m[b*5 + o] = acc;
            }
        }

        // gated + biased vector scatter-add
        const float4* br4 = reinterpret_cast<const float4*>(bsh + r * 20);
        float* op = out + (size_t)d * OUT_FEAT;
#pragma unroll
        for (int k = 0; k < 5; k++) {
            float4 bv = br4[k];
            red_add_v4(op + 4*k,
                       gate * (m[4*k+0] + bv.x),
                       gate * (m[4*k+1] + bv.y),
                       gate * (m[4*k+2] + bv.z),
                       gate * (m[4*k+3] + bv.w));
        }
    }
}

// ---------------------------------------------------------------------------
// Kernel C: in-place ReLU
// ---------------------------------------------------------------------------
__global__ void relu_kernel(float* __restrict__ out, int n4) {
    int i = blockIdx.x * blockDim.x + threadIdx.x;
    if (i >= n4) return;
    float4* p = reinterpret_cast<float4*>(out);
    float4 v = p[i];
    v.x = fmaxf(v.x, 0.0f);
    v.y = fmaxf(v.y, 0.0f);
    v.z = fmaxf(v.z, 0.0f);
    v.w = fmaxf(v.w, 0.0f);
    p[i] = v;
}

// ---------------------------------------------------------------------------
// Launch
// ---------------------------------------------------------------------------
extern "C" void kernel_launch(void* const* d_in, const int* in_sizes, int n_in,
                              void* d_out, int out_size) {
    const float* h           = (const float*)d_in[0];
    const float* weight      = (const float*)d_in[1];
    const float* bias_term   = (const float*)d_in[2];
    const float* gate_weight = (const float*)d_in[3];
    const float* gate_bias   = (const float*)d_in[4];
    const float* loop_weight = (const float*)d_in[5];
    const int*   edge_src    = (const int*)d_in[6];
    const int*   edge_dst    = (const int*)d_in[7];
    const int*   etype       = (const int*)d_in[8];
    float* out = (float*)d_out;

    // A: self-loop message into out (+ zero bin cursors)
    loop_msg_kernel<<<(N_NODES + 255) / 256, 256>>>(h, loop_weight, out);

    // Block-aggregated binning by relation into fixed-capacity bins
    scatter_kernel<<<512, 256>>>(edge_src, edge_dst, etype);

    // Edge kernel, 2 CTAs/SM
    cudaFuncSetAttribute(edge_kernel, cudaFuncAttributeMaxDynamicSharedMemorySize, SM_BYTES);
    edge_kernel<<<296, 512, SM_BYTES>>>(h, weight, bias_term, gate_weight, gate_bias, out);

    // ReLU in place
    int n4 = (N_NODES * OUT_FEAT) / 4;
    relu_kernel<<<(n4 + 255) / 256, 256>>>(out, n4);
}